// round 2
// baseline (speedup 1.0000x reference)
#include <cuda_runtime.h>
#include <cuda_bf16.h>
#include <cstdint>

#define DEVFN __device__ __forceinline__

constexpr int NROWS  = 8192;
constexpr int DDIM   = 256;
constexpr int MT     = 128;          // tile size (rows and cols)
constexpr int NTILES = NROWS / MT;   // 64 column tiles
constexpr float EXP_SCALE = 2.8853900817779268f; // (1/tau)*log2(e), tau=0.5

// Scratch (device globals; no runtime allocation allowed)
__device__ __align__(16) __nv_bfloat16 Z1g[NROWS * DDIM];
__device__ __align__(16) __nv_bfloat16 Z2g[NROWS * DDIM];
__device__ float RSg[4][NROWS];   // row sums of exp for S11, S22, S12, S21
__device__ float DGg[3][NROWS];   // scaled diagonals: s11_ii/tau, s22_ii/tau, s12_ii/tau

// ---------------- helpers ----------------
DEVFN uint32_t smem_u32(const void* p) {
    return (uint32_t)__cvta_generic_to_shared(p);
}
DEVFN void cp_commit() { asm volatile("cp.async.commit_group;" ::: "memory"); }
DEVFN void cp_wait0()  { asm volatile("cp.async.wait_group 0;" ::: "memory"); }

DEVFN float fexp2(float x) {
    float y;
    asm("ex2.approx.ftz.f32 %0, %1;" : "=f"(y) : "f"(x));
    return y;
}

DEVFN void ldm4(uint32_t& r0, uint32_t& r1, uint32_t& r2, uint32_t& r3, uint32_t addr) {
    asm volatile("ldmatrix.sync.aligned.m8n8.x4.shared.b16 {%0,%1,%2,%3}, [%4];"
                 : "=r"(r0), "=r"(r1), "=r"(r2), "=r"(r3) : "r"(addr));
}

DEVFN void mma_bf16(float* c, const uint32_t* a, uint32_t b0, uint32_t b1) {
    asm volatile(
        "mma.sync.aligned.m16n8k16.row.col.f32.bf16.bf16.f32 "
        "{%0,%1,%2,%3}, {%4,%5,%6,%7}, {%8,%9}, {%0,%1,%2,%3};"
        : "+f"(c[0]), "+f"(c[1]), "+f"(c[2]), "+f"(c[3])
        : "r"(a[0]), "r"(a[1]), "r"(a[2]), "r"(a[3]), "r"(b0), "r"(b1));
}

// ---------------- SMEM layout ----------------
// Tile = 128 rows x 256 bf16 (512 B/row), 16B chunks XOR-swizzled within 128B groups.
constexpr int SM_ACC   = 0;      // 128 floats cross-half combine
constexpr int SM_A     = 1024;
constexpr int SM_B0    = SM_A  + 65536;
constexpr int SM_B1    = SM_B0 + 65536;
constexpr int SM_TOTAL = SM_B1 + 65536;   // 197632 B

// swizzled byte offset of (row, 16B-chunk) within a tile
DEVFN uint32_t tile_off(int row, int chunk) {
    return (uint32_t)(row * 512 + ((((chunk & 7) ^ (row & 7))) << 4) + ((chunk & 24) << 4));
}

// Load a 128x256 bf16 tile into swizzled SMEM via cp.async (16B chunks)
DEVFN void load_tile(uint32_t sdst, const __nv_bfloat16* __restrict__ src, int tid) {
    #pragma unroll
    for (int it = 0; it < 16; ++it) {
        int idx = tid + it * 256;           // 4096 chunks total
        int row = idx >> 5;                 // 0..127
        int c   = idx & 31;                 // chunk within row
        const __nv_bfloat16* gp = src + ((size_t)row << 8) + (c << 3);
        asm volatile("cp.async.cg.shared.global [%0], [%1], 16;"
                     :: "r"(sdst + tile_off(row, c)), "l"(gp) : "memory");
    }
}

// ---------------- Kernel 1: normalize + exact diagonals ----------------
__global__ void __launch_bounds__(256) norm_kernel(const float* __restrict__ H1,
                                                   const float* __restrict__ H2) {
    int gw   = (blockIdx.x * 256 + threadIdx.x) >> 5;   // row index
    int lane = threadIdx.x & 31;
    const float* p1 = H1 + (size_t)gw * DDIM;
    const float* p2 = H2 + (size_t)gw * DDIM;
    float a[8], b[8], ss1 = 0.f, ss2 = 0.f;
    #pragma unroll
    for (int k = 0; k < 8; ++k) {
        a[k] = p1[lane + 32 * k];
        b[k] = p2[lane + 32 * k];
        ss1 += a[k] * a[k];
        ss2 += b[k] * b[k];
    }
    #pragma unroll
    for (int o = 16; o; o >>= 1) {
        ss1 += __shfl_xor_sync(0xFFFFFFFFu, ss1, o);
        ss2 += __shfl_xor_sync(0xFFFFFFFFu, ss2, o);
    }
    float inv1 = 1.f / fmaxf(sqrtf(ss1), 1e-12f);
    float inv2 = 1.f / fmaxf(sqrtf(ss2), 1e-12f);
    __nv_bfloat16* q1 = Z1g + (size_t)gw * DDIM;
    __nv_bfloat16* q2 = Z2g + (size_t)gw * DDIM;
    float d11 = 0.f, d22 = 0.f, d12 = 0.f;
    #pragma unroll
    for (int k = 0; k < 8; ++k) {
        __nv_bfloat16 z1 = __float2bfloat16(a[k] * inv1);
        __nv_bfloat16 z2 = __float2bfloat16(b[k] * inv2);
        q1[lane + 32 * k] = z1;
        q2[lane + 32 * k] = z2;
        float f1 = __bfloat162float(z1), f2 = __bfloat162float(z2);
        d11 += f1 * f1; d22 += f2 * f2; d12 += f1 * f2;
    }
    #pragma unroll
    for (int o = 16; o; o >>= 1) {
        d11 += __shfl_xor_sync(0xFFFFFFFFu, d11, o);
        d22 += __shfl_xor_sync(0xFFFFFFFFu, d22, o);
        d12 += __shfl_xor_sync(0xFFFFFFFFu, d12, o);
    }
    if (lane == 0) {
        DGg[0][gw] = 2.f * d11;
        DGg[1][gw] = 2.f * d22;
        DGg[2][gw] = 2.f * d12;
    }
}

// ---------------- Kernel 2: fused Gram row-sums of exp (mma.sync path) ----------------
// grid (64, 4): blockIdx.x = row block, blockIdx.y = job m
// m=0: S11 (Z1,Z1)  m=1: S22 (Z2,Z2)  m=2: S12 (Z1,Z2)  m=3: S21 (Z2,Z1)
// 8 warps: wm = wid&3 (32-row slice), wn = wid>>2 (64-col half). Warp tile 32x64.
__global__ void __launch_bounds__(256, 1) gram_kernel() {
    extern __shared__ char smem[];
    const uint32_t sb = smem_u32(smem);
    const int tid  = threadIdx.x;
    const int wid  = tid >> 5;
    const int lane = tid & 31;
    const int wm = wid & 3;
    const int wn = wid >> 2;
    const int rb = blockIdx.x;
    const int m  = blockIdx.y;

    const __nv_bfloat16* X = (m == 0 || m == 2) ? Z1g : Z2g;
    const __nv_bfloat16* Y = (m == 0 || m == 3) ? Z1g : Z2g;

    // Preload A (this CTA's 128 rows of X) and B tile 0
    load_tile(sb + SM_A,  X + (size_t)rb * MT * DDIM, tid);
    load_tile(sb + SM_B0, Y, tid);
    cp_commit(); cp_wait0();
    __syncthreads();

    // ldmatrix lane address components (constant per thread)
    const int l7   = lane & 7;          // row-within-8
    const int qA_r = (lane >> 3) & 1;   // A: +8 rows for quads 1,3
    const int qA_c = (lane >> 4);       // A: +1 chunk for quads 2,3
    const int qB_r = (lane >> 4);       // B: +8 rows for quads 2,3
    const int qB_c = (lane >> 3) & 1;   // B: +1 chunk for quads 1,3

    float rs[4] = {0.f, 0.f, 0.f, 0.f}; // row-sum accumulators (rows g, g+8, g+16, g+24)

    for (int j = 0; j < NTILES; ++j) {
        const uint32_t bsm = sb + ((j & 1) ? SM_B1 : SM_B0);
        if (j + 1 < NTILES) {
            load_tile(sb + (((j + 1) & 1) ? SM_B1 : SM_B0),
                      Y + (size_t)(j + 1) * MT * DDIM, tid);
            cp_commit();
        }

        float acc[2][8][4];
        #pragma unroll
        for (int ms = 0; ms < 2; ++ms)
            #pragma unroll
            for (int ns = 0; ns < 8; ++ns)
                #pragma unroll
                for (int c = 0; c < 4; ++c) acc[ms][ns][c] = 0.f;

        #pragma unroll
        for (int ks = 0; ks < 16; ++ks) {
            const int ch = 2 * ks;
            uint32_t a0[4], a1[4];
            {
                int row = wm * 32 + l7 + 8 * qA_r;
                ldm4(a0[0], a0[1], a0[2], a0[3], sb + SM_A + tile_off(row,      ch + qA_c));
                ldm4(a1[0], a1[1], a1[2], a1[3], sb + SM_A + tile_off(row + 16, ch + qA_c));
            }
            uint32_t bf[4][4];
            #pragma unroll
            for (int np = 0; np < 4; ++np) {
                int row = wn * 64 + np * 16 + l7 + 8 * qB_r;
                ldm4(bf[np][0], bf[np][1], bf[np][2], bf[np][3],
                     bsm + tile_off(row, ch + qB_c));
            }
            #pragma unroll
            for (int np = 0; np < 4; ++np) {
                #pragma unroll
                for (int sub = 0; sub < 2; ++sub) {
                    mma_bf16(acc[0][2 * np + sub], a0, bf[np][2 * sub], bf[np][2 * sub + 1]);
                    mma_bf16(acc[1][2 * np + sub], a1, bf[np][2 * sub], bf[np][2 * sub + 1]);
                }
            }
        }

        // epilogue: exp and accumulate per-row sums
        #pragma unroll
        for (int ms = 0; ms < 2; ++ms)
            #pragma unroll
            for (int ns = 0; ns < 8; ++ns) {
                rs[2 * ms]     += fexp2(acc[ms][ns][0] * EXP_SCALE)
                                + fexp2(acc[ms][ns][1] * EXP_SCALE);
                rs[2 * ms + 1] += fexp2(acc[ms][ns][2] * EXP_SCALE)
                                + fexp2(acc[ms][ns][3] * EXP_SCALE);
            }

        if (j + 1 < NTILES) cp_wait0();
        __syncthreads();
    }

    // reduce across the 4 lanes of each quad (same row, different cols)
    #pragma unroll
    for (int r = 0; r < 4; ++r) {
        rs[r] += __shfl_xor_sync(0xFFFFFFFFu, rs[r], 1);
        rs[r] += __shfl_xor_sync(0xFFFFFFFFu, rs[r], 2);
    }

    float* accs = (float*)(smem + SM_ACC);
    const int g = lane >> 2;
    if ((lane & 3) == 0 && wn == 1) {
        #pragma unroll
        for (int r = 0; r < 4; ++r) accs[wm * 32 + 8 * r + g] = rs[r];
    }
    __syncthreads();
    if ((lane & 3) == 0 && wn == 0) {
        #pragma unroll
        for (int r = 0; r < 4; ++r) {
            int lr = wm * 32 + 8 * r + g;
            RSg[m][rb * MT + lr] = rs[r] + accs[lr];
        }
    }
}

// ---------------- Kernel 3: final reduction ----------------
__global__ void __launch_bounds__(256) reduce_kernel(float* out) {
    float s = 0.f;
    for (int i = threadIdx.x; i < NROWS; i += 256) {
        float den1 = RSg[0][i] + RSg[2][i] - __expf(DGg[0][i]);
        float den2 = RSg[1][i] + RSg[3][i] - __expf(DGg[1][i]);
        s += 0.5f * (__logf(den1) + __logf(den2)) - DGg[2][i];
    }
    #pragma unroll
    for (int o = 16; o; o >>= 1) s += __shfl_xor_sync(0xFFFFFFFFu, s, o);
    __shared__ float ws[8];
    if ((threadIdx.x & 31) == 0) ws[threadIdx.x >> 5] = s;
    __syncthreads();
    if (threadIdx.x < 8) {
        s = ws[threadIdx.x];
        #pragma unroll
        for (int o = 4; o; o >>= 1) s += __shfl_xor_sync(0xFFu, s, o);
        if (threadIdx.x == 0) out[0] = s / (float)NROWS;
    }
}

// ---------------- launch ----------------
extern "C" void kernel_launch(void* const* d_in, const int* in_sizes, int n_in,
                              void* d_out, int out_size) {
    const float* H1 = (const float*)d_in[0];
    const float* H2 = (const float*)d_in[1];
    float* out = (float*)d_out;

    norm_kernel<<<NROWS * 32 / 256, 256>>>(H1, H2);

    static bool attr_set = false;
    if (!attr_set) {
        cudaFuncSetAttribute(gram_kernel, cudaFuncAttributeMaxDynamicSharedMemorySize, SM_TOTAL);
        attr_set = true;
    }
    gram_kernel<<<dim3(NTILES, 4), 256, SM_TOTAL>>>();

    reduce_kernel<<<1, 256>>>(out);
}

// round 3
// speedup vs baseline: 1.7676x; 1.7676x over previous
#include <cuda_runtime.h>
#include <cuda_bf16.h>
#include <cstdint>

#define DEVFN __device__ __forceinline__

constexpr int NROWS  = 8192;
constexpr int DDIM   = 256;
constexpr int MT     = 128;          // tile size (rows and cols)
constexpr int NTILES = NROWS / MT;   // 64 column tiles
// exp(s/tau) = exp2(s * 2*log2(e)); fold sqrt of that into each operand
constexpr float SQRT_SCALE = 1.6986436005760748f;  // sqrt(2*log2(e))
constexpr float LN2F = 0.6931471805599453f;

// Scratch (device globals; no runtime allocation allowed)
__device__ __align__(16) __nv_bfloat16 Z1g[NROWS * DDIM];
__device__ __align__(16) __nv_bfloat16 Z2g[NROWS * DDIM];
__device__ float RSg[4][NROWS];   // row sums of exp for S11, S22, S12, S21
__device__ float DGg[3][NROWS];   // log2-domain diagonals (scaled dots)

// ---------------- helpers ----------------
DEVFN uint32_t smem_u32(const void* p) {
    return (uint32_t)__cvta_generic_to_shared(p);
}
DEVFN void cp_commit() { asm volatile("cp.async.commit_group;" ::: "memory"); }
DEVFN void cp_wait0()  { asm volatile("cp.async.wait_group 0;" ::: "memory"); }

DEVFN float fexp2(float x) {
    float y;
    asm("ex2.approx.ftz.f32 %0, %1;" : "=f"(y) : "f"(x));
    return y;
}

DEVFN void ldm4(uint32_t& r0, uint32_t& r1, uint32_t& r2, uint32_t& r3, uint32_t addr) {
    asm volatile("ldmatrix.sync.aligned.m8n8.x4.shared.b16 {%0,%1,%2,%3}, [%4];"
                 : "=r"(r0), "=r"(r1), "=r"(r2), "=r"(r3) : "r"(addr));
}

DEVFN void mma_bf16(float* c, const uint32_t* a, uint32_t b0, uint32_t b1) {
    asm volatile(
        "mma.sync.aligned.m16n8k16.row.col.f32.bf16.bf16.f32 "
        "{%0,%1,%2,%3}, {%4,%5,%6,%7}, {%8,%9}, {%0,%1,%2,%3};"
        : "+f"(c[0]), "+f"(c[1]), "+f"(c[2]), "+f"(c[3])
        : "r"(a[0]), "r"(a[1]), "r"(a[2]), "r"(a[3]), "r"(b0), "r"(b1));
}

// ---------------- SMEM layout ----------------
constexpr int SM_A     = 0;
constexpr int SM_B0    = SM_A  + 65536;
constexpr int SM_B1    = SM_B0 + 65536;
constexpr int SM_TOTAL = SM_B1 + 65536;   // 196608 B

// swizzled byte offset of (row, 16B-chunk) within a 128x256 bf16 tile
DEVFN uint32_t tile_off(int row, int chunk) {
    return (uint32_t)(row * 512 + ((((chunk & 7) ^ (row & 7))) << 4) + ((chunk & 24) << 4));
}

// Load a 128x256 bf16 tile into swizzled SMEM via cp.async (16B chunks), 512 threads
DEVFN void load_tile(uint32_t sdst, const __nv_bfloat16* __restrict__ src, int tid) {
    #pragma unroll
    for (int it = 0; it < 8; ++it) {
        int idx = tid + it * 512;           // 4096 chunks total
        int row = idx >> 5;                 // 0..127
        int c   = idx & 31;                 // chunk within row
        const __nv_bfloat16* gp = src + ((size_t)row << 8) + (c << 3);
        asm volatile("cp.async.cg.shared.global [%0], [%1], 16;"
                     :: "r"(sdst + tile_off(row, c)), "l"(gp) : "memory");
    }
}

// ---------------- Kernel 1: normalize (pre-scaled) + diagonals + RS zero ----------------
__global__ void __launch_bounds__(256) norm_kernel(const float* __restrict__ H1,
                                                   const float* __restrict__ H2) {
    // zero RSg (accumulated via atomics by gram_kernel each replay)
    if (blockIdx.x < 128) ((float*)RSg)[blockIdx.x * 256 + threadIdx.x] = 0.f;

    int gw   = (blockIdx.x * 256 + threadIdx.x) >> 5;   // row index
    int lane = threadIdx.x & 31;
    const float* p1 = H1 + (size_t)gw * DDIM;
    const float* p2 = H2 + (size_t)gw * DDIM;
    float a[8], b[8], ss1 = 0.f, ss2 = 0.f;
    #pragma unroll
    for (int k = 0; k < 8; ++k) {
        a[k] = p1[lane + 32 * k];
        b[k] = p2[lane + 32 * k];
        ss1 += a[k] * a[k];
        ss2 += b[k] * b[k];
    }
    #pragma unroll
    for (int o = 16; o; o >>= 1) {
        ss1 += __shfl_xor_sync(0xFFFFFFFFu, ss1, o);
        ss2 += __shfl_xor_sync(0xFFFFFFFFu, ss2, o);
    }
    float inv1 = SQRT_SCALE / fmaxf(sqrtf(ss1), 1e-12f);
    float inv2 = SQRT_SCALE / fmaxf(sqrtf(ss2), 1e-12f);
    __nv_bfloat16* q1 = Z1g + (size_t)gw * DDIM;
    __nv_bfloat16* q2 = Z2g + (size_t)gw * DDIM;
    float d11 = 0.f, d22 = 0.f, d12 = 0.f;
    #pragma unroll
    for (int k = 0; k < 8; ++k) {
        __nv_bfloat16 z1 = __float2bfloat16(a[k] * inv1);
        __nv_bfloat16 z2 = __float2bfloat16(b[k] * inv2);
        q1[lane + 32 * k] = z1;
        q2[lane + 32 * k] = z2;
        float f1 = __bfloat162float(z1), f2 = __bfloat162float(z2);
        d11 += f1 * f1; d22 += f2 * f2; d12 += f1 * f2;
    }
    #pragma unroll
    for (int o = 16; o; o >>= 1) {
        d11 += __shfl_xor_sync(0xFFFFFFFFu, d11, o);
        d22 += __shfl_xor_sync(0xFFFFFFFFu, d22, o);
        d12 += __shfl_xor_sync(0xFFFFFFFFu, d12, o);
    }
    if (lane == 0) {
        DGg[0][gw] = d11;   // log2-domain diagonals
        DGg[1][gw] = d22;
        DGg[2][gw] = d12;
    }
}

// ---------------- Kernel 2: fused Gram row/col-sums of exp with symmetry ----------------
// 128 CTAs:
//   bx in [0,32):   S11 symmetric, pairs row blocks (p, 63-p), tiles j >= rb
//   bx in [32,64):  S22 symmetric, same pairing
//   bx in [64,128): S12 full, rb = bx-64, row sums -> RSg[2], col sums -> RSg[3]
// 16 warps: wm = wid&3 (32-row slice), wn = wid>>2 (32-col slice). Warp tile 32x32.
__global__ void __launch_bounds__(512, 1) gram_kernel() {
    extern __shared__ char smem[];
    const uint32_t sb = smem_u32(smem);
    const int tid  = threadIdx.x;
    const int wid  = tid >> 5;
    const int lane = tid & 31;
    const int wm = wid & 3;
    const int wn = wid >> 2;
    const int bx = blockIdx.x;

    const __nv_bfloat16 *X, *Y;
    int mrow, mcol, seg0, seg1, nseg;
    bool sym;
    if (bx < 64) {
        int p = bx & 31;
        bool s22 = (bx >= 32);
        X = Y = s22 ? Z2g : Z1g;
        mrow = mcol = s22 ? 1 : 0;
        seg0 = p; seg1 = 63 - p; nseg = 2; sym = true;
    } else {
        X = Z1g; Y = Z2g;
        mrow = 2; mcol = 3;
        seg0 = bx - 64; seg1 = 0; nseg = 1; sym = false;
    }

    // ldmatrix lane address components (constant per thread)
    const int l7   = lane & 7;
    const int qA_r = (lane >> 3) & 1;
    const int qA_c = (lane >> 4);
    const int qB_r = (lane >> 4);
    const int qB_c = (lane >> 3) & 1;
    const int l3   = lane & 3;
    const int g    = lane >> 2;

    for (int s = 0; s < nseg; ++s) {
        const int rb = s ? seg1 : seg0;
        const int jstart = sym ? rb : 0;

        load_tile(sb + SM_A, X + (size_t)rb * MT * DDIM, tid);
        load_tile(sb + ((jstart & 1) ? SM_B1 : SM_B0), Y + (size_t)jstart * MT * DDIM, tid);
        cp_commit(); cp_wait0();
        __syncthreads();

        float rs[4] = {0.f, 0.f, 0.f, 0.f};

        for (int j = jstart; j < NTILES; ++j) {
            const uint32_t bsm = sb + ((j & 1) ? SM_B1 : SM_B0);
            if (j + 1 < NTILES) {
                load_tile(sb + (((j + 1) & 1) ? SM_B1 : SM_B0),
                          Y + (size_t)(j + 1) * MT * DDIM, tid);
                cp_commit();
            }

            float acc[2][4][4];
            #pragma unroll
            for (int ms = 0; ms < 2; ++ms)
                #pragma unroll
                for (int ns = 0; ns < 4; ++ns)
                    #pragma unroll
                    for (int c = 0; c < 4; ++c) acc[ms][ns][c] = 0.f;

            #pragma unroll
            for (int ks = 0; ks < 16; ++ks) {
                const int ch = 2 * ks;
                uint32_t a0[4], a1[4];
                {
                    int row = wm * 32 + l7 + 8 * qA_r;
                    ldm4(a0[0], a0[1], a0[2], a0[3], sb + SM_A + tile_off(row,      ch + qA_c));
                    ldm4(a1[0], a1[1], a1[2], a1[3], sb + SM_A + tile_off(row + 16, ch + qA_c));
                }
                uint32_t bf[2][4];
                #pragma unroll
                for (int np = 0; np < 2; ++np) {
                    int row = wn * 32 + np * 16 + l7 + 8 * qB_r;
                    ldm4(bf[np][0], bf[np][1], bf[np][2], bf[np][3],
                         bsm + tile_off(row, ch + qB_c));
                }
                #pragma unroll
                for (int np = 0; np < 2; ++np) {
                    #pragma unroll
                    for (int sub = 0; sub < 2; ++sub) {
                        mma_bf16(acc[0][2 * np + sub], a0, bf[np][2 * sub], bf[np][2 * sub + 1]);
                        mma_bf16(acc[1][2 * np + sub], a1, bf[np][2 * sub], bf[np][2 * sub + 1]);
                    }
                }
            }

            // epilogue: exp2, accumulate row sums (registers) and col sums (per tile)
            float col[8];
            #pragma unroll
            for (int k = 0; k < 8; ++k) col[k] = 0.f;
            #pragma unroll
            for (int ms = 0; ms < 2; ++ms)
                #pragma unroll
                for (int ns = 0; ns < 4; ++ns) {
                    float e0 = fexp2(acc[ms][ns][0]);
                    float e1 = fexp2(acc[ms][ns][1]);
                    float e2 = fexp2(acc[ms][ns][2]);
                    float e3 = fexp2(acc[ms][ns][3]);
                    rs[2 * ms]     += e0 + e1;
                    rs[2 * ms + 1] += e2 + e3;
                    col[2 * ns]     += e0 + e2;
                    col[2 * ns + 1] += e1 + e3;
                }

            const bool do_col = (!sym) || (j != rb);
            if (do_col) {
                #pragma unroll
                for (int k = 0; k < 8; ++k) {
                    col[k] += __shfl_xor_sync(0xFFFFFFFFu, col[k], 4);
                    col[k] += __shfl_xor_sync(0xFFFFFFFFu, col[k], 8);
                    col[k] += __shfl_xor_sync(0xFFFFFFFFu, col[k], 16);
                }
                if (lane < 4) {
                    float* dst = &RSg[mcol][j * MT + wn * 32];
                    #pragma unroll
                    for (int ns = 0; ns < 4; ++ns) {
                        atomicAdd(dst + ns * 8 + 2 * lane,     col[2 * ns]);
                        atomicAdd(dst + ns * 8 + 2 * lane + 1, col[2 * ns + 1]);
                    }
                }
            }

            if (j + 1 < NTILES) cp_wait0();
            __syncthreads();
        }

        // flush row sums for this segment
        #pragma unroll
        for (int r = 0; r < 4; ++r) {
            rs[r] += __shfl_xor_sync(0xFFFFFFFFu, rs[r], 1);
            rs[r] += __shfl_xor_sync(0xFFFFFFFFu, rs[r], 2);
        }
        if (l3 == 0) {
            float* dst = &RSg[mrow][rb * MT + wm * 32];
            #pragma unroll
            for (int ms = 0; ms < 2; ++ms)
                #pragma unroll
                for (int cc = 0; cc < 2; ++cc)
                    atomicAdd(dst + ms * 16 + 8 * cc + g, rs[2 * ms + cc]);
        }
        __syncthreads();  // before next segment overwrites A
    }
}

// ---------------- Kernel 3: final reduction ----------------
__global__ void __launch_bounds__(256) reduce_kernel(float* out) {
    float s = 0.f;
    for (int i = threadIdx.x; i < NROWS; i += 256) {
        float den1 = RSg[0][i] + RSg[2][i] - exp2f(DGg[0][i]);
        float den2 = RSg[1][i] + RSg[3][i] - exp2f(DGg[1][i]);
        s += 0.5f * (__logf(den1) + __logf(den2)) - DGg[2][i] * LN2F;
    }
    #pragma unroll
    for (int o = 16; o; o >>= 1) s += __shfl_xor_sync(0xFFFFFFFFu, s, o);
    __shared__ float ws[8];
    if ((threadIdx.x & 31) == 0) ws[threadIdx.x >> 5] = s;
    __syncthreads();
    if (threadIdx.x < 8) {
        s = ws[threadIdx.x];
        #pragma unroll
        for (int o = 4; o; o >>= 1) s += __shfl_xor_sync(0xFFu, s, o);
        if (threadIdx.x == 0) out[0] = s / (float)NROWS;
    }
}

// ---------------- launch ----------------
extern "C" void kernel_launch(void* const* d_in, const int* in_sizes, int n_in,
                              void* d_out, int out_size) {
    const float* H1 = (const float*)d_in[0];
    const float* H2 = (const float*)d_in[1];
    float* out = (float*)d_out;

    norm_kernel<<<NROWS * 32 / 256, 256>>>(H1, H2);

    static bool attr_set = false;
    if (!attr_set) {
        cudaFuncSetAttribute(gram_kernel, cudaFuncAttributeMaxDynamicSharedMemorySize, SM_TOTAL);
        attr_set = true;
    }
    gram_kernel<<<128, 512, SM_TOTAL>>>();

    reduce_kernel<<<1, 256>>>(out);
}